// round 11
// baseline (speedup 1.0000x reference)
#include <cuda_runtime.h>
#include <math.h>

#define N_RAYS_C 131072
#define N_HIT_C  65536
#define K4_GRID  1216        // 152 SMs x 8 blocks (GB300)
#define NWARP    (K4_GRID * 8)
#define NPK      7           // ceil(65536 / 9728)

// ---------------- device state (zero at load; every replay restores zeros)
__device__ __align__(16) unsigned g_h1[2048]; // hist (top 11 bits of err key)
__device__ unsigned g_nvalid;
__device__ unsigned g_cnt1, g_cnt4;
__device__ float    g_thresh;
__device__ float    g_sums[4];                // sum_dm, sum_m, acc_neighbor, acc_empty

// 256-thread exclusive scan; sh must hold 8 unsigned
__device__ __forceinline__ unsigned block_scan_excl_256(unsigned v, unsigned* sh) {
    int lane = threadIdx.x & 31, w = threadIdx.x >> 5;
    unsigned x = v;
    #pragma unroll
    for (int o = 1; o < 32; o <<= 1) {
        unsigned y = __shfl_up_sync(0xFFFFFFFFu, x, o);
        if (lane >= o) x += y;
    }
    if (lane == 31) sh[w] = x;
    __syncthreads();
    if (w == 0 && lane < 8) {
        unsigned s = sh[lane], xx = s;
        #pragma unroll
        for (int o = 1; o < 8; o <<= 1) {
            unsigned y = __shfl_up_sync(0x000000FFu, xx, o);
            if (lane >= o) xx += y;
        }
        sh[lane] = xx - s;
    }
    __syncthreads();
    return (x - v) + sh[w];
}

// last-block ticket
__device__ __forceinline__ bool last_block(unsigned* cnt) {
    __threadfence();
    __syncthreads();
    __shared__ unsigned s_last;
    if (threadIdx.x == 0) s_last = (atomicAdd(cnt, 1u) == gridDim.x - 1u) ? 1u : 0u;
    __syncthreads();
    if (!s_last) return false;
    if (threadIdx.x == 0) *cnt = 0;
    return true;
}

// err key from raw inputs (pure function; 0xFFFFFFFF if invalid)
__device__ __forceinline__ unsigned err_key(float d, float r, float m) {
    bool valid = (r > 0.0f) && (m > 1e-7f) && (r < 80.0f);
    return valid ? __float_as_uint(fabsf(d - r)) : 0xFFFFFFFFu;
}

// ========== K1 (primary): pure median -> g_thresh, zero g_sums ==========
__global__ void k1(const float* __restrict__ dp,
                   const float* __restrict__ rg,
                   const float* __restrict__ mp) {
    cudaTriggerProgrammaticLaunchCompletion();   // let k4 dispatch immediately
    __shared__ unsigned sh[2048];
    __shared__ unsigned scnt;
    __shared__ unsigned s_med[2];
    int t = threadIdx.x;
    for (int b = t; b < 2048; b += 256) sh[b] = 0;
    if (t == 0) scnt = 0;
    __syncthreads();

    int i = blockIdx.x * 256 + t;
    unsigned key = err_key(dp[i], rg[i], mp[i]);
    bool valid = (key != 0xFFFFFFFFu);
    if (valid) atomicAdd(&sh[key >> 21], 1u);
    unsigned bal = __ballot_sync(0xFFFFFFFFu, valid);
    if ((t & 31) == 0 && bal) atomicAdd(&scnt, (unsigned)__popc(bal));
    __syncthreads();
    for (int b = t; b < 2048; b += 256) {
        unsigned c = sh[b];
        if (c) atomicAdd(&g_h1[b], c);
    }
    if (t == 0 && scnt) atomicAdd(&g_nvalid, scnt);

    if (!last_block(&g_cnt1)) return;

    // fused select over 2048 bins (8/thread, in registers)
    unsigned n = g_nvalid;
    if (t == 0) g_nvalid = 0;
    unsigned c[8];
    unsigned lsum = 0;
    #pragma unroll
    for (int k = 0; k < 8; k++) { c[k] = g_h1[t * 8 + k]; lsum += c[k]; }
    #pragma unroll
    for (int k = 0; k < 8; k++) g_h1[t * 8 + k] = 0;   // re-zero for next replay

    if (n) {
        __shared__ unsigned shs[8];
        unsigned excl = block_scan_excl_256(lsum, shs);
        unsigned ranks[2] = { (n - 1) >> 1, n >> 1 };
        #pragma unroll
        for (int jr = 0; jr < 2; jr++) {
            unsigned rr = ranks[jr];
            if (rr >= excl && rr < excl + lsum) {
                unsigned run = excl;
                #pragma unroll
                for (int k = 0; k < 8; k++) {
                    if (rr < run + c[k]) {
                        // bin midpoint (guard band 14x >> 12.5% bin width)
                        s_med[jr] = ((unsigned)(t * 8 + k) << 21) | 0x100000u;
                        break;
                    }
                    run += c[k];
                }
            }
        }
    }
    __syncthreads();
    if (t == 0) {
        float thr = -1.0f;                    // n==0: mask nothing (NaN-median)
        if (n) thr = 100.0f * 0.5f * (__uint_as_float(s_med[0]) + __uint_as_float(s_med[1]));
        g_thresh = thr;
        g_sums[0] = g_sums[1] = g_sums[2] = g_sums[3] = 0.0f;
    }
}

// unmasked 4-float chunk
__device__ __forceinline__ void pack_chunk(float4 d4, float4 w4, float gt,
                                           float& ln, float& le) {
    #pragma unroll
    for (int c = 0; c < 4; c++) {
        float dd = (&d4.x)[c], w = (&w4.x)[c];
        float x = dd - gt;
        float pdf = __expf(-4.5f * x * x) * 1.1968268412042982f;   // 3/sqrt(2pi)
        float td = w - pdf;
        ln += (fabsf(x) <= 1.0f) ? td * td : 0.0f;
        le += (x < -1.0f) ? w * w : 0.0f;
    }
}

// ========== K4 (secondary, PDL): streams + gathers pre-sync; masks post-sync ==========
__global__ void __launch_bounds__(256)
k4(const float4* __restrict__ ds4, const float4* __restrict__ vw4,
   const int*    __restrict__ rih, const float*  __restrict__ rg,
   const float*  __restrict__ dp,  const float*  __restrict__ mp,
   float* __restrict__ out) {
    __shared__ unsigned s_key[8][NPK];
    __shared__ float2   s_pp[8][NPK];
    int t = threadIdx.x;
    int gtid = blockIdx.x * 256 + t;
    int lane = t & 31, wid = t >> 5;
    int gw = blockIdx.x * 8 + wid;          // 0..9727

    // ---- pre-sync: per-pack gt/key gathers (inputs only; warp-uniform) ----
    int rays[NPK];
    #pragma unroll
    for (int k = 0; k < NPK; k++) {
        int p = gw + k * NWARP;
        rays[k] = (p < N_HIT_C) ? rih[p] : 0;
    }
    float gts[NPK];
    #pragma unroll
    for (int k = 0; k < NPK; k++) {
        int p = gw + k * NWARP;
        if (p < N_HIT_C) {
            float rr = rg[rays[k]];
            gts[k] = rr;
            if (lane == 0) s_key[wid][k] = err_key(dp[rays[k]], rr, mp[rays[k]]);
        } else {
            gts[k] = 0.0f;
            if (lane == 0) s_key[wid][k] = 0xFFFFFFFFu;
        }
    }

    // ---- pre-sync: depth-loss per-ray key + diff (inputs only) ----
    unsigned dkey = 0xFFFFFFFFu;
    float ddiff = 0.0f;
    if (gtid < N_RAYS_C) {
        float d = dp[gtid], r = rg[gtid], m = mp[gtid];
        dkey = err_key(d, r, m);
        if (dkey != 0xFFFFFFFFu) ddiff = fabsf(log1pf(d) - log1pf(r));
    }

    // ---- pre-sync: stream 67MB, unmasked per-pack partials -> smem ----
    #pragma unroll
    for (int k = 0; k < NPK; k++) {
        int p = gw + k * NWARP;
        float ln = 0.0f, le = 0.0f;
        if (p < N_HIT_C) {
            float4 d4 = ds4[p * 32 + lane];
            float4 w4 = vw4[p * 32 + lane];
            pack_chunk(d4, w4, gts[k], ln, le);
        }
        #pragma unroll
        for (int o = 16; o; o >>= 1) {
            ln += __shfl_down_sync(0xFFFFFFFFu, ln, o);
            le += __shfl_down_sync(0xFFFFFFFFu, le, o);
        }
        if (lane == 0) s_pp[wid][k] = make_float2(ln, le);
    }
    __syncwarp();

    // ---- wait for k1's threshold ----
    cudaGridDependencySynchronize();
    const float thr = g_thresh;

    float dm = 0.0f, mm = 0.0f;
    if (gtid < N_RAYS_C && __uint_as_float(dkey) < thr) { mm = 1.0f; dm = ddiff; }

    float accn = 0.0f, acce = 0.0f;
    if (lane < NPK) {
        if (__uint_as_float(s_key[wid][lane]) < thr) {
            float2 pp = s_pp[wid][lane];
            accn = pp.x; acce = pp.y;
        }
    }

    // ---- combined block reduction (4 accumulators) ----
    #pragma unroll
    for (int o = 16; o; o >>= 1) {
        dm   += __shfl_down_sync(0xFFFFFFFFu, dm,   o);
        mm   += __shfl_down_sync(0xFFFFFFFFu, mm,   o);
        accn += __shfl_down_sync(0xFFFFFFFFu, accn, o);
        acce += __shfl_down_sync(0xFFFFFFFFu, acce, o);
    }
    __shared__ float s0[8], s1[8], s2[8], s3[8];
    if (lane == 0) { s0[wid] = dm; s1[wid] = mm; s2[wid] = accn; s3[wid] = acce; }
    __syncthreads();
    if (t == 0) {
        float a = 0, b = 0, c = 0, e = 0;
        #pragma unroll
        for (int k = 0; k < 8; k++) { a += s0[k]; b += s1[k]; c += s2[k]; e += s3[k]; }
        atomicAdd(&g_sums[0], a);
        atomicAdd(&g_sums[1], b);
        atomicAdd(&g_sums[2], c);
        atomicAdd(&g_sums[3], e);
    }

    if (!last_block(&g_cnt4)) return;
    if (t == 0) {
        out[0] = g_sums[0] / fmaxf(g_sums[1], 1.0f);           // W_DEPTH = 1
        out[1] = 0.1f * (g_sums[2] * (1.0f / 65536.0f));       // W_LOS * mean
        out[2] = 0.1f * (g_sums[3] * (1.0f / 65536.0f));
    }
}

extern "C" void kernel_launch(void* const* d_in, const int* in_sizes, int n_in,
                              void* d_out, int out_size) {
    const float* dp  = (const float*)d_in[0];   // depth_pred   [131072]
    const float* rg  = (const float*)d_in[1];   // ranges       [131072]
    const float* mp  = (const float*)d_in[2];   // mask_pred    [131072]
    const float* ds  = (const float*)d_in[3];   // depth_samples[8388608]
    const float* vw  = (const float*)d_in[4];   // vw           [8388608]
    const int*   rih = (const int*)d_in[5];     // rays_inds_hit[65536]
    float* out = (float*)d_out;

    k1<<<512, 256>>>(dp, rg, mp);

    // PDL: k4 dispatches under k1; its pre-sync phase touches only inputs.
    cudaLaunchConfig_t cfg = {};
    cfg.gridDim  = dim3(K4_GRID, 1, 1);
    cfg.blockDim = dim3(256, 1, 1);
    cfg.dynamicSmemBytes = 0;
    cfg.stream = 0;
    cudaLaunchAttribute attrs[1];
    attrs[0].id = cudaLaunchAttributeProgrammaticStreamSerialization;
    attrs[0].val.programmaticStreamSerializationAllowed = 1;
    cfg.attrs = attrs;
    cfg.numAttrs = 1;
    cudaLaunchKernelEx(&cfg, k4,
                       (const float4*)ds, (const float4*)vw, rih, rg, dp, mp, out);
}

// round 13
// speedup vs baseline: 1.0892x; 1.0892x over previous
#include <cuda_runtime.h>
#include <math.h>

#define N_RAYS_C 131072
#define N_HIT_C  65536
#define K4_GRID  1216        // 152 SMs x 8 blocks = one wave @256 thr (GB300)
#define K1_GRID  128         // 32768 threads, 4 rays/thread (float4)

// ---------------- device state (zero at load; every replay restores zeros)
__device__ __align__(16) unsigned g_key[N_RAYS_C];  // err bits (valid) or 0xFFFFFFFF
__device__ float2   g_pack[N_HIT_C];          // per-pack {gt, key_bits_as_float}
__device__ __align__(16) unsigned g_h1[2048]; // hist (top 11 bits)
__device__ unsigned g_nvalid;
__device__ unsigned g_cnt1, g_cnt4;
__device__ float    g_thresh;
__device__ float    g_sums[4];                // sum_dm, sum_m, acc_neighbor, acc_empty

// 256-thread exclusive scan; sh must hold 8 unsigned
__device__ __forceinline__ unsigned block_scan_excl_256(unsigned v, unsigned* sh) {
    int lane = threadIdx.x & 31, w = threadIdx.x >> 5;
    unsigned x = v;
    #pragma unroll
    for (int o = 1; o < 32; o <<= 1) {
        unsigned y = __shfl_up_sync(0xFFFFFFFFu, x, o);
        if (lane >= o) x += y;
    }
    if (lane == 31) sh[w] = x;
    __syncthreads();
    if (w == 0 && lane < 8) {
        unsigned s = sh[lane], xx = s;
        #pragma unroll
        for (int o = 1; o < 8; o <<= 1) {
            unsigned y = __shfl_up_sync(0x000000FFu, xx, o);
            if (lane >= o) xx += y;
        }
        sh[lane] = xx - s;
    }
    __syncthreads();
    return (x - v) + sh[w];
}

// last-block ticket
__device__ __forceinline__ bool last_block(unsigned* cnt, unsigned grid) {
    __threadfence();
    __syncthreads();
    __shared__ unsigned s_last;
    if (threadIdx.x == 0) s_last = (atomicAdd(cnt, 1u) == grid - 1u) ? 1u : 0u;
    __syncthreads();
    if (!s_last) return false;
    if (threadIdx.x == 0) *cnt = 0;
    return true;
}

// err key from raw inputs (pure function; 0xFFFFFFFF if invalid)
__device__ __forceinline__ unsigned err_key(float d, float r, float m) {
    bool valid = (r > 0.0f) && (m > 1e-7f) && (r < 80.0f);
    return valid ? __float_as_uint(fabsf(d - r)) : 0xFFFFFFFFu;
}

// ========== K1: vectorized keys + 2048-bin hist + pack precompute + select ==========
__global__ void __launch_bounds__(256)
k1(const float4* __restrict__ dp4, const float4* __restrict__ rg4,
   const float4* __restrict__ mp4,
   const float*  __restrict__ dp,  const float*  __restrict__ rg,
   const float*  __restrict__ mp,  const int*    __restrict__ rih) {
    __shared__ unsigned sh[2048];
    __shared__ unsigned scnt;
    __shared__ unsigned s_med[2];
    int t = threadIdx.x;
    int gtid = blockIdx.x * 256 + t;        // 0..32767
    for (int b = t; b < 2048; b += 256) sh[b] = 0;
    if (t == 0) scnt = 0;
    __syncthreads();

    // 4 rays per thread, vectorized
    float4 d4 = dp4[gtid], r4 = rg4[gtid], m4 = mp4[gtid];
    uint4 keys;
    keys.x = err_key(d4.x, r4.x, m4.x);
    keys.y = err_key(d4.y, r4.y, m4.y);
    keys.z = err_key(d4.z, r4.z, m4.z);
    keys.w = err_key(d4.w, r4.w, m4.w);
    ((uint4*)g_key)[gtid] = keys;
    unsigned nv = 0;
    #pragma unroll
    for (int c = 0; c < 4; c++) {
        unsigned k = (&keys.x)[c];
        if (k != 0xFFFFFFFFu) { atomicAdd(&sh[k >> 21], 1u); nv++; }
    }
    // warp-reduce valid count
    #pragma unroll
    for (int o = 16; o; o >>= 1) nv += __shfl_down_sync(0xFFFFFFFFu, nv, o);
    if ((t & 31) == 0 && nv) atomicAdd(&scnt, nv);

    // per-pack precompute: 2 packs per thread (grid-strided)
    #pragma unroll
    for (int k = 0; k < 2; k++) {
        int p = gtid + k * 32768;
        int ray = rih[p];
        float rr = rg[ray];
        g_pack[p] = make_float2(rr, __uint_as_float(err_key(dp[ray], rr, mp[ray])));
    }

    __syncthreads();
    for (int b = t; b < 2048; b += 256) {
        unsigned c = sh[b];
        if (c) atomicAdd(&g_h1[b], c);
    }
    if (t == 0 && scnt) atomicAdd(&g_nvalid, scnt);

    if (!last_block(&g_cnt1, K1_GRID)) return;

    // ---- fused select over 2048 bins (8 per thread, in registers) ----
    unsigned n = g_nvalid;
    if (t == 0) g_nvalid = 0;
    unsigned c[8];
    unsigned lsum = 0;
    #pragma unroll
    for (int k = 0; k < 8; k++) { c[k] = g_h1[t * 8 + k]; lsum += c[k]; }
    #pragma unroll
    for (int k = 0; k < 8; k++) g_h1[t * 8 + k] = 0;   // re-zero for next replay

    if (n) {
        __shared__ unsigned shs[8];
        unsigned excl = block_scan_excl_256(lsum, shs);
        unsigned ranks[2] = { (n - 1) >> 1, n >> 1 };
        #pragma unroll
        for (int jr = 0; jr < 2; jr++) {
            unsigned rr = ranks[jr];
            if (rr >= excl && rr < excl + lsum) {
                unsigned run = excl;
                #pragma unroll
                for (int k = 0; k < 8; k++) {
                    if (rr < run + c[k]) {
                        // bin midpoint: top-11 prefix + half of low 21 bits
                        // (guard band 14x >> 12.5% bin width -> mask unchanged)
                        s_med[jr] = ((unsigned)(t * 8 + k) << 21) | 0x100000u;
                        break;
                    }
                    run += c[k];
                }
            }
        }
    }
    __syncthreads();
    if (t == 0) {
        float thr = -1.0f;                       // n==0: mask nothing (NaN-median)
        if (n) thr = 100.0f * 0.5f * (__uint_as_float(s_med[0]) + __uint_as_float(s_med[1]));
        g_thresh = thr;
        g_sums[0] = g_sums[1] = g_sums[2] = g_sums[3] = 0.0f;
    }
}

// one pack's 4-float chunk (branchless)
__device__ __forceinline__ void pack_chunk(float4 d4, float4 w4, float gt, bool msk,
                                           float& accn, float& acce) {
    float ln = 0.0f, le = 0.0f;
    #pragma unroll
    for (int c = 0; c < 4; c++) {
        float dd = (&d4.x)[c], w = (&w4.x)[c];
        float x = dd - gt;
        float pdf = __expf(-4.5f * x * x) * 1.1968268412042982f;   // 3/sqrt(2pi)
        float td = w - pdf;
        ln += (fabsf(x) <= 1.0f) ? td * td : 0.0f;
        le += (x < -1.0f) ? w * w : 0.0f;
    }
    if (msk) { accn += ln; acce += le; }
}

// ============ K4: streaming pack loss (warp-per-pack, one wave) + depth loss + finalize ============
__global__ void __launch_bounds__(256)
k4(const float4* __restrict__ ds4, const float4* __restrict__ vw4,
   const float*  __restrict__ rg,  const float*  __restrict__ dp,
   float* __restrict__ out) {
    int t = threadIdx.x;
    int gtid = blockIdx.x * 256 + t;        // grid covers 311296 >= 131072
    int lane = t & 31, wid = t >> 5;
    const float thr = g_thresh;

    // ---- depth loss (first 131072 threads) ----
    float dm = 0.0f, mm = 0.0f;
    if (gtid < N_RAYS_C) {
        float kf = __uint_as_float(g_key[gtid]);   // NaN if invalid -> compare false
        if (kf < thr) {
            mm = 1.0f;
            dm = fabsf(log1pf(dp[gtid]) - log1pf(rg[gtid]));
        }
    }

    // ---- pack loss: warp-per-pack grid-stride; per-iter loads, TLP hides latency ----
    const int NWARP = K4_GRID * 8;          // 9728 warps
    int gw = blockIdx.x * 8 + wid;
    float accn = 0.0f, acce = 0.0f;
    for (int p = gw; p < N_HIT_C; p += NWARP) {
        float2 gk = g_pack[p];              // warp-uniform 8B broadcast
        float4 d4 = ds4[p * 32 + lane];
        float4 w4 = vw4[p * 32 + lane];
        pack_chunk(d4, w4, gk.x, (gk.y < thr), accn, acce);
    }

    // ---- combined block reduction (4 accumulators) ----
    #pragma unroll
    for (int o = 16; o; o >>= 1) {
        dm   += __shfl_down_sync(0xFFFFFFFFu, dm,   o);
        mm   += __shfl_down_sync(0xFFFFFFFFu, mm,   o);
        accn += __shfl_down_sync(0xFFFFFFFFu, accn, o);
        acce += __shfl_down_sync(0xFFFFFFFFu, acce, o);
    }
    __shared__ float s0[8], s1[8], s2[8], s3[8];
    if (lane == 0) { s0[wid] = dm; s1[wid] = mm; s2[wid] = accn; s3[wid] = acce; }
    __syncthreads();
    if (t == 0) {
        float a = 0, b = 0, c = 0, e = 0;
        #pragma unroll
        for (int k = 0; k < 8; k++) { a += s0[k]; b += s1[k]; c += s2[k]; e += s3[k]; }
        atomicAdd(&g_sums[0], a);
        atomicAdd(&g_sums[1], b);
        atomicAdd(&g_sums[2], c);
        atomicAdd(&g_sums[3], e);
    }

    if (!last_block(&g_cnt4, K4_GRID)) return;
    if (t == 0) {
        out[0] = g_sums[0] / fmaxf(g_sums[1], 1.0f);           // W_DEPTH = 1
        out[1] = 0.1f * (g_sums[2] * (1.0f / 65536.0f));       // W_LOS * mean
        out[2] = 0.1f * (g_sums[3] * (1.0f / 65536.0f));
    }
}

extern "C" void kernel_launch(void* const* d_in, const int* in_sizes, int n_in,
                              void* d_out, int out_size) {
    const float* dp  = (const float*)d_in[0];   // depth_pred   [131072]
    const float* rg  = (const float*)d_in[1];   // ranges       [131072]
    const float* mp  = (const float*)d_in[2];   // mask_pred    [131072]
    const float* ds  = (const float*)d_in[3];   // depth_samples[8388608]
    const float* vw  = (const float*)d_in[4];   // vw           [8388608]
    const int*   rih = (const int*)d_in[5];     // rays_inds_hit[65536]
    float* out = (float*)d_out;

    k1<<<K1_GRID, 256>>>((const float4*)dp, (const float4*)rg, (const float4*)mp,
                         dp, rg, mp, rih);
    k4<<<K4_GRID, 256>>>((const float4*)ds, (const float4*)vw, rg, dp, out);
}

// round 14
// speedup vs baseline: 1.1723x; 1.0762x over previous
#include <cuda_runtime.h>
#include <math.h>

#define N_RAYS_C 131072
#define N_HIT_C  65536
#define K4_GRID  1216        // 152 SMs x 8 blocks = one wave @256 thr (GB300)
#define K1_GRID  128         // 32768 threads, 4 rays/thread (float4)

// ---------------- device state (zero at load; every replay restores zeros)
__device__ __align__(16) unsigned g_key[N_RAYS_C];  // err bits (valid) or 0xFFFFFFFF
__device__ float2   g_pack[N_HIT_C];          // per-pack {gt, key_bits_as_float}
__device__ __align__(16) unsigned g_h1[2048]; // hist (top 11 bits)
__device__ unsigned g_nvalid;
__device__ unsigned g_cnt1, g_cnt4;
__device__ float    g_thresh;
__device__ float    g_sums[4];                // sum_dm, sum_m, acc_neighbor, acc_empty

// 256-thread exclusive scan; sh must hold 8 unsigned
__device__ __forceinline__ unsigned block_scan_excl_256(unsigned v, unsigned* sh) {
    int lane = threadIdx.x & 31, w = threadIdx.x >> 5;
    unsigned x = v;
    #pragma unroll
    for (int o = 1; o < 32; o <<= 1) {
        unsigned y = __shfl_up_sync(0xFFFFFFFFu, x, o);
        if (lane >= o) x += y;
    }
    if (lane == 31) sh[w] = x;
    __syncthreads();
    if (w == 0 && lane < 8) {
        unsigned s = sh[lane], xx = s;
        #pragma unroll
        for (int o = 1; o < 8; o <<= 1) {
            unsigned y = __shfl_up_sync(0x000000FFu, xx, o);
            if (lane >= o) xx += y;
        }
        sh[lane] = xx - s;
    }
    __syncthreads();
    return (x - v) + sh[w];
}

// last-block ticket
__device__ __forceinline__ bool last_block(unsigned* cnt, unsigned grid) {
    __threadfence();
    __syncthreads();
    __shared__ unsigned s_last;
    if (threadIdx.x == 0) s_last = (atomicAdd(cnt, 1u) == grid - 1u) ? 1u : 0u;
    __syncthreads();
    if (!s_last) return false;
    if (threadIdx.x == 0) *cnt = 0;
    return true;
}

// err key from raw inputs (pure function; 0xFFFFFFFF if invalid)
__device__ __forceinline__ unsigned err_key(float d, float r, float m) {
    bool valid = (r > 0.0f) && (m > 1e-7f) && (r < 80.0f);
    return valid ? __float_as_uint(fabsf(d - r)) : 0xFFFFFFFFu;
}

// ========== K1: vectorized keys + 2048-bin hist + pack precompute + select ==========
__global__ void __launch_bounds__(256)
k1(const float4* __restrict__ dp4, const float4* __restrict__ rg4,
   const float4* __restrict__ mp4,
   const float*  __restrict__ dp,  const float*  __restrict__ rg,
   const float*  __restrict__ mp,  const int*    __restrict__ rih) {
    __shared__ unsigned sh[2048];
    __shared__ unsigned scnt;
    __shared__ unsigned s_med[2];
    int t = threadIdx.x;
    int gtid = blockIdx.x * 256 + t;        // 0..32767
    for (int b = t; b < 2048; b += 256) sh[b] = 0;
    if (t == 0) scnt = 0;
    __syncthreads();

    // 4 rays per thread, vectorized
    float4 d4 = dp4[gtid], r4 = rg4[gtid], m4 = mp4[gtid];
    uint4 keys;
    keys.x = err_key(d4.x, r4.x, m4.x);
    keys.y = err_key(d4.y, r4.y, m4.y);
    keys.z = err_key(d4.z, r4.z, m4.z);
    keys.w = err_key(d4.w, r4.w, m4.w);
    ((uint4*)g_key)[gtid] = keys;
    unsigned nv = 0;
    #pragma unroll
    for (int c = 0; c < 4; c++) {
        unsigned k = (&keys.x)[c];
        if (k != 0xFFFFFFFFu) { atomicAdd(&sh[k >> 21], 1u); nv++; }
    }
    // warp-reduce valid count
    #pragma unroll
    for (int o = 16; o; o >>= 1) nv += __shfl_down_sync(0xFFFFFFFFu, nv, o);
    if ((t & 31) == 0 && nv) atomicAdd(&scnt, nv);

    // per-pack precompute: 2 packs per thread (grid-strided)
    #pragma unroll
    for (int k = 0; k < 2; k++) {
        int p = gtid + k * 32768;
        int ray = rih[p];
        float rr = rg[ray];
        g_pack[p] = make_float2(rr, __uint_as_float(err_key(dp[ray], rr, mp[ray])));
    }

    __syncthreads();
    for (int b = t; b < 2048; b += 256) {
        unsigned c = sh[b];
        if (c) atomicAdd(&g_h1[b], c);
    }
    if (t == 0 && scnt) atomicAdd(&g_nvalid, scnt);

    if (!last_block(&g_cnt1, K1_GRID)) return;

    // ---- fused select over 2048 bins (8 per thread, in registers) ----
    unsigned n = g_nvalid;
    if (t == 0) g_nvalid = 0;
    unsigned c[8];
    unsigned lsum = 0;
    #pragma unroll
    for (int k = 0; k < 8; k++) { c[k] = g_h1[t * 8 + k]; lsum += c[k]; }
    #pragma unroll
    for (int k = 0; k < 8; k++) g_h1[t * 8 + k] = 0;   // re-zero for next replay

    if (n) {
        __shared__ unsigned shs[8];
        unsigned excl = block_scan_excl_256(lsum, shs);
        unsigned ranks[2] = { (n - 1) >> 1, n >> 1 };
        #pragma unroll
        for (int jr = 0; jr < 2; jr++) {
            unsigned rr = ranks[jr];
            if (rr >= excl && rr < excl + lsum) {
                unsigned run = excl;
                #pragma unroll
                for (int k = 0; k < 8; k++) {
                    if (rr < run + c[k]) {
                        // bin midpoint: top-11 prefix + half of low 21 bits
                        // (guard band 14x >> 12.5% bin width -> mask unchanged)
                        s_med[jr] = ((unsigned)(t * 8 + k) << 21) | 0x100000u;
                        break;
                    }
                    run += c[k];
                }
            }
        }
    }
    __syncthreads();
    if (t == 0) {
        float thr = -1.0f;                       // n==0: mask nothing (NaN-median)
        if (n) thr = 100.0f * 0.5f * (__uint_as_float(s_med[0]) + __uint_as_float(s_med[1]));
        g_thresh = thr;
        g_sums[0] = g_sums[1] = g_sums[2] = g_sums[3] = 0.0f;
    }
}

// one pack's 4-float chunk (branchless)
__device__ __forceinline__ void pack_chunk(float4 d4, float4 w4, float gt, bool msk,
                                           float& accn, float& acce) {
    float ln = 0.0f, le = 0.0f;
    #pragma unroll
    for (int c = 0; c < 4; c++) {
        float dd = (&d4.x)[c], w = (&w4.x)[c];
        float x = dd - gt;
        float pdf = __expf(-4.5f * x * x) * 1.1968268412042982f;   // 3/sqrt(2pi)
        float td = w - pdf;
        ln += (fabsf(x) <= 1.0f) ? td * td : 0.0f;
        le += (x < -1.0f) ? w * w : 0.0f;
    }
    if (msk) { accn += ln; acce += le; }
}

// ============ K4: streaming pack loss (warp-per-pack, TRUE one wave: <=32 regs)
//               + depth loss + finalize ============
__global__ void __launch_bounds__(256, 8)
k4(const float4* __restrict__ ds4, const float4* __restrict__ vw4,
   const float*  __restrict__ rg,  const float*  __restrict__ dp,
   float* __restrict__ out) {
    int t = threadIdx.x;
    int gtid = blockIdx.x * 256 + t;        // grid covers 311296 >= 131072
    int lane = t & 31, wid = t >> 5;
    const float thr = g_thresh;

    // ---- pack loss: warp-per-pack grid-stride; per-iter loads, TLP hides latency ----
    const int NWARP = K4_GRID * 8;          // 9728 warps
    int gw = blockIdx.x * 8 + wid;
    float accn = 0.0f, acce = 0.0f;
    for (int p = gw; p < N_HIT_C; p += NWARP) {
        float2 gk = g_pack[p];              // warp-uniform 8B broadcast
        float4 d4 = ds4[p * 32 + lane];
        float4 w4 = vw4[p * 32 + lane];
        pack_chunk(d4, w4, gk.x, (gk.y < thr), accn, acce);
    }

    // ---- depth loss (first 131072 threads) — after loop to shorten live ranges ----
    float dm = 0.0f, mm = 0.0f;
    if (gtid < N_RAYS_C) {
        float kf = __uint_as_float(g_key[gtid]);   // NaN if invalid -> compare false
        if (kf < thr) {
            mm = 1.0f;
            dm = fabsf(log1pf(dp[gtid]) - log1pf(rg[gtid]));
        }
    }

    // ---- combined block reduction (4 accumulators) ----
    #pragma unroll
    for (int o = 16; o; o >>= 1) {
        dm   += __shfl_down_sync(0xFFFFFFFFu, dm,   o);
        mm   += __shfl_down_sync(0xFFFFFFFFu, mm,   o);
        accn += __shfl_down_sync(0xFFFFFFFFu, accn, o);
        acce += __shfl_down_sync(0xFFFFFFFFu, acce, o);
    }
    __shared__ float s0[8], s1[8], s2[8], s3[8];
    if (lane == 0) { s0[wid] = dm; s1[wid] = mm; s2[wid] = accn; s3[wid] = acce; }
    __syncthreads();
    if (t == 0) {
        float a = 0, b = 0, c = 0, e = 0;
        #pragma unroll
        for (int k = 0; k < 8; k++) { a += s0[k]; b += s1[k]; c += s2[k]; e += s3[k]; }
        atomicAdd(&g_sums[0], a);
        atomicAdd(&g_sums[1], b);
        atomicAdd(&g_sums[2], c);
        atomicAdd(&g_sums[3], e);
    }

    if (!last_block(&g_cnt4, K4_GRID)) return;
    if (t == 0) {
        out[0] = g_sums[0] / fmaxf(g_sums[1], 1.0f);           // W_DEPTH = 1
        out[1] = 0.1f * (g_sums[2] * (1.0f / 65536.0f));       // W_LOS * mean
        out[2] = 0.1f * (g_sums[3] * (1.0f / 65536.0f));
    }
}

extern "C" void kernel_launch(void* const* d_in, const int* in_sizes, int n_in,
                              void* d_out, int out_size) {
    const float* dp  = (const float*)d_in[0];   // depth_pred   [131072]
    const float* rg  = (const float*)d_in[1];   // ranges       [131072]
    const float* mp  = (const float*)d_in[2];   // mask_pred    [131072]
    const float* ds  = (const float*)d_in[3];   // depth_samples[8388608]
    const float* vw  = (const float*)d_in[4];   // vw           [8388608]
    const int*   rih = (const int*)d_in[5];     // rays_inds_hit[65536]
    float* out = (float*)d_out;

    k1<<<K1_GRID, 256>>>((const float4*)dp, (const float4*)rg, (const float4*)mp,
                         dp, rg, mp, rih);
    k4<<<K4_GRID, 256>>>((const float4*)ds, (const float4*)vw, rg, dp, out);
}